// round 13
// baseline (speedup 1.0000x reference)
#include <cuda_runtime.h>
#include <cuda_bf16.h>
#include <math.h>

#define NGT      20
#define MCELL    4096
#define MANC     (MCELL*42)
#define TOTANC   (8*MANC)
#define KPATCH   2304
#define MAXTASK  8192
#define MAXSITE  8192
#define PCAP     4096
#define CAND_MAX 32768
#define CAND_THR 131072u
#define TIE_MAX  256
#define REGY     10
#define REGX     10
#define KCH      576         // KPATCH/4

// ---- device state: ALL zero-init at load; K5 restores this state each replay ----
__device__ unsigned g_maxgt[8*NGT];
__device__ int      g_candCnt;
__device__ unsigned g_candU[CAND_MAX];
__device__ int      g_candJ[CAND_MAX];
__device__ int      g_taskCnt, g_siteCnt, g_P;
__device__ int      g_doneB, g_doneH;
__device__ int      g_taskJ[MAXTASK];
__device__ int      g_taskFlag[MAXTASK];
__device__ int      g_taskSite[MAXTASK];
__device__ float    g_taskOff[MAXTASK*4];
__device__ int      g_cellOwner[8*MCELL];      // 0 = unclaimed, else task+1
__device__ int      g_siteCell[MAXSITE];
__device__ int      g_siteOfTask[MAXTASK];
__device__ float    g_patch[(size_t)MAXSITE*KPATCH];
__device__ float    g_hidP[4][(size_t)MAXSITE*512];
__device__ float    g_accPos, g_accNeg, g_accReg;

__device__ __forceinline__ unsigned rotl32(unsigned v, int d){ return (v<<d)|(v>>(32-d)); }

__device__ __forceinline__ unsigned long long pk2(float lo, float hi){
    unsigned long long r;
    asm("mov.b64 %0, {%1,%2};" : "=l"(r) : "f"(lo), "f"(hi));
    return r;
}
__device__ __forceinline__ void upk2(float& lo, float& hi, unsigned long long v){
    asm("mov.b64 {%0,%1}, %2;" : "=f"(lo), "=f"(hi) : "l"(v));
}
__device__ __forceinline__ void fma2(unsigned long long& d, unsigned long long a, unsigned long long b){
    asm("fma.rn.f32x2 %0, %1, %2, %3;" : "=l"(d) : "l"(a), "l"(b), "l"(d));
}

// JAX partitionable threefry: element j -> threefry2x32(key=(0,7),(0,j)); draw = (o0^o1)>>9
__device__ __forceinline__ unsigned threefry_u(unsigned j){
    unsigned x0 = 0u, x1 = j;
    const unsigned ks0 = 0u, ks1 = 7u, ks2 = 0x1BD11BDDu;
    x0 += ks0; x1 += ks1;
#define TF_R4(A,B,C,D) { x0+=x1; x1=rotl32(x1,A); x1^=x0; \
                         x0+=x1; x1=rotl32(x1,B); x1^=x0; \
                         x0+=x1; x1=rotl32(x1,C); x1^=x0; \
                         x0+=x1; x1=rotl32(x1,D); x1^=x0; }
    TF_R4(13,15,26,6);  x0 += ks1; x1 += ks2 + 1u;
    TF_R4(17,29,16,24); x0 += ks2; x1 += ks0 + 2u;
    TF_R4(13,15,26,6);  x0 += ks0; x1 += ks1 + 3u;
    TF_R4(17,29,16,24); x0 += ks1; x1 += ks2 + 4u;
    TF_R4(13,15,26,6);  x0 += ks2; x1 += ks0 + 5u;
#undef TF_R4
    return (x0 ^ x1) >> 9;
}

// IoU V1 — all plain RN, no contraction. Bit-exact vs reference. DO NOT CHANGE.
__device__ __forceinline__ float iou_one(float a0,float a1,float a2,float a3,
                                         float areaA,
                                         const float* g, float gw0, float gw1){
    float t0 = fmaxf(a0, g[0]), t1 = fmaxf(a1, g[1]);
    float q0 = fminf(a2, g[2]), q1 = fminf(a3, g[3]);
    float w0 = fmaxf(__fsub_rn(q0, t0), 0.0f);
    float w1 = fmaxf(__fsub_rn(q1, t1), 0.0f);
    float inter = __fmul_rn(w0, w1);
    float ag    = __fmul_rn(gw0, gw1);
    float sum   = __fadd_rn(areaA, ag);
    float den   = __fsub_rn(sum, inter);
    return __fdiv_rn(inter, den);
}

__device__ __forceinline__ float softplusf(float x){
    return fmaxf(x, 0.0f) + log1pf(expf(-fabsf(x)));
}

__device__ __forceinline__ void anc_coords(int a, int y, int x,
                                           float& a0, float& a1, float& a2, float& a3){
    const double SC[6] = {2.0, 2.5, 3.0, 3.5, 4.0, 5.0};
    const double RA[7] = {0.5, 1.5, 2.0, 2.5, 3.0, 3.5, 4.0};
    double s = SC[a/7], ar = RA[a%7];
    double h = (16.0*s) * sqrt(ar);
    double w = (16.0*s) * sqrt(1.0/ar);
    float b0 = (float)(8.0 - h/2.0);
    float b1 = (float)(8.0 - w/2.0);
    float b2 = (float)(8.0 + h/2.0);
    float b3 = (float)(8.0 + w/2.0);
    double sy = (double)(y*16), sx = (double)(x*16);
    a0 = (float)((double)b0 + sy);
    a1 = (float)((double)b1 + sx);
    a2 = (float)((double)b2 + sy);
    a3 = (float)((double)b3 + sx);
}

// ---------------- K1: threefry candidates || passA ----------------
__global__ void k1(const float* __restrict__ gt){
    if (blockIdx.x < TOTANC/512){
        int j = blockIdx.x*512 + threadIdx.x;
        unsigned u = threefry_u((unsigned)j);
        if (u < CAND_THR){
            int slot = atomicAdd(&g_candCnt, 1);
            if (slot < CAND_MAX){ g_candU[slot] = u; g_candJ[slot] = j; }
        }
        return;
    }
    __shared__ float sg[NGT][4];
    __shared__ int   sval[NGT];
    __shared__ float sgw[NGT][2];
    __shared__ unsigned smax[NGT];
    int tid = threadIdx.x;
    int pb = blockIdx.x - TOTANC/512;
    int b = pb / REGY, y = pb % REGY;
    if (tid < NGT*4){
        int n = tid >> 2, k = tid & 3;
        float r = gt[(b*NGT+n)*4 + k];
        sg[n][k] = (r == -1.0f) ? -1.0f : r * 0.0625f;
    }
    if (tid < NGT) smax[tid] = 0u;
    __syncthreads();
    if (tid < NGT){
        sval[tid] = (sg[tid][0] >= 0.0f) ? 1 : 0;
        sgw[tid][0] = __fsub_rn(sg[tid][2], sg[tid][0]);
        sgw[tid][1] = __fsub_rn(sg[tid][3], sg[tid][1]);
    }
    __syncthreads();
    int x = tid / 42, a = tid % 42;
    if (x < REGX){
        float a0,a1,a2,a3; anc_coords(a, y, x, a0,a1,a2,a3);
        float areaA = __fmul_rn(__fsub_rn(a2,a0), __fsub_rn(a3,a1));
        #pragma unroll
        for (int n = 0; n < NGT; n++){
            if (sval[n]){
                float v = iou_one(a0,a1,a2,a3, areaA, sg[n], sgw[n][0], sgw[n][1]);
                if (v > 0.0f) atomicMax(&smax[n], __float_as_uint(v));
            }
        }
    }
    __syncthreads();
    if (tid < NGT && smax[tid]) atomicMax(&g_maxgt[b*NGT + tid], smax[tid]);
}

// ---------------- K2: passB; last block freezes P AND runs select+tail inline ----------------
__global__ void k2(const float* __restrict__ gt){
    __shared__ float sg[NGT][4];
    __shared__ int   sval[NGT];
    __shared__ float sgw[NGT][2];
    __shared__ float smaxg[NGT];
    __shared__ int   sLast;
    __shared__ unsigned hist[1024];
    __shared__ unsigned h2[128];
    __shared__ int tieJ[TIE_MAX];
    __shared__ int sTie, sBin, sR2, sCnt;
    __shared__ unsigned sUstar, sC1;
    int tid = threadIdx.x;
    int D = blockDim.x;
    int b = blockIdx.x / REGY, y = blockIdx.x % REGY;
    if (tid < NGT*4){
        int n = tid >> 2, k = tid & 3;
        float r = gt[(b*NGT+n)*4 + k];
        sg[n][k] = (r == -1.0f) ? -1.0f : r * 0.0625f;
    }
    __syncthreads();
    if (tid < NGT){
        sval[tid] = (sg[tid][0] >= 0.0f) ? 1 : 0;
        sgw[tid][0] = __fsub_rn(sg[tid][2], sg[tid][0]);
        sgw[tid][1] = __fsub_rn(sg[tid][3], sg[tid][1]);
        smaxg[tid] = __uint_as_float(g_maxgt[b*NGT + tid]);
    }
    __syncthreads();
    int x = tid / 42, a = tid % 42;
    if (x < REGX){
        float a0,a1,a2,a3; anc_coords(a, y, x, a0,a1,a2,a3);
        float areaA = __fmul_rn(__fsub_rn(a2,a0), __fsub_rn(a3,a1));
        float best = -1.0f; int bestn = 0; bool pos = false;
        #pragma unroll
        for (int n = 0; n < NGT; n++){
            float v = sval[n] ? iou_one(a0,a1,a2,a3, areaA, sg[n], sgw[n][0], sgw[n][1]) : 0.0f;
            if (v > best){ best = v; bestn = n; }
            if (sval[n] && smaxg[n] > 0.0f && v == smaxg[n]) pos = true;
        }
        if (pos){
            int slot = atomicAdd(&g_taskCnt, 1);
            if (slot < MAXTASK){
                int j = ((b*MCELL) + y*64 + x)*42 + a;
                g_taskJ[slot] = j;
                g_taskFlag[slot] = 1;
                const float* G = sg[bestn];
                float acy = __fmul_rn(__fadd_rn(a0, a2), 0.5f);
                float acx = __fmul_rn(__fadd_rn(a1, a3), 0.5f);
                float asy = __fsub_rn(a2, a0), asx = __fsub_rn(a3, a1);
                float gcy = __fmul_rn(__fadd_rn(G[0], G[2]), 0.5f);
                float gcx = __fmul_rn(__fadd_rn(G[1], G[3]), 0.5f);
                float gsy = __fsub_rn(G[2], G[0]), gsx = __fsub_rn(G[3], G[1]);
                g_taskOff[slot*4+0] = __fdiv_rn(__fsub_rn(gcy, acy), asy);
                g_taskOff[slot*4+1] = __fdiv_rn(__fsub_rn(gcx, acx), asx);
                g_taskOff[slot*4+2] = logf(__fdiv_rn(gsy, asy));
                g_taskOff[slot*4+3] = logf(__fdiv_rn(gsx, asx));
            }
        }
    }
    __syncthreads();
    if (tid == 0){
        __threadfence();
        sLast = (atomicAdd(&g_doneB, 1) == gridDim.x - 1);
    }
    __syncthreads();
    if (!sLast) return;

    // ======== last block: freeze P, then select + tail (formerly k3) ========
    if (tid == 0){
        int P = g_taskCnt; if (P > PCAP) P = PCAP;
        g_P = P; g_doneB = 0; sTie = 0;
    }
    for (int i = tid; i < 1024; i += D) hist[i] = 0u;
    __syncthreads();
    int C = g_candCnt; if (C > CAND_MAX) C = CAND_MAX;
    int P = g_P;
    if (P > 0){
        for (int i = tid; i < C; i += D) atomicAdd(&hist[g_candU[i] >> 7], 1u);
    }
    __syncthreads();
    if (tid == 0){
        int bin = -1; unsigned cum = 0;
        if (P > 0){
            for (int q = 0; q < 1024; q++){
                unsigned h = hist[q];
                if (cum + h >= (unsigned)P){ bin = q; break; }
                cum += h;
            }
        }
        sBin = bin; sC1 = cum;
    }
    __syncthreads();
    int bin = sBin;
    unsigned C1 = sC1;
    for (int i = tid; i < 128; i += D) h2[i] = 0u;
    __syncthreads();
    if (bin >= 0){
        for (int i = tid; i < C; i += D){
            unsigned u = g_candU[i];
            if ((int)(u >> 7) == bin) atomicAdd(&h2[u & 127u], 1u);
        }
    }
    __syncthreads();
    if (tid == 0 && bin >= 0){
        unsigned cum = C1; int vS = 0; unsigned Cless = C1;
        for (int v = 0; v < 128; v++){
            unsigned c = h2[v];
            if (cum + c >= (unsigned)P){ vS = v; Cless = cum; break; }
            cum += c;
        }
        sUstar = ((unsigned)bin << 7) | (unsigned)vS;
        sR2 = P - (int)Cless;
    }
    __syncthreads();
    if (bin >= 0){
        unsigned us = sUstar;
        for (int i = tid; i < C; i += D){
            unsigned u = g_candU[i];
            if (u < us){
                int slot = atomicAdd(&g_taskCnt, 1);
                if (slot < MAXTASK){ g_taskJ[slot] = g_candJ[i]; g_taskFlag[slot] = 0; }
            } else if (u == us){
                int t = atomicAdd(&sTie, 1);
                if (t < TIE_MAX) tieJ[t] = g_candJ[i];
            }
        }
    }
    __syncthreads();
    int T = sTie; if (T > TIE_MAX) T = TIE_MAX;
    int R2 = (bin >= 0) ? sR2 : 0;
    for (int i = tid; i < T; i += D){
        int ji = tieJ[i], rank = 0;
        for (int q = 0; q < T; q++) if (tieJ[q] < ji) rank++;
        if (rank < R2){
            int slot = atomicAdd(&g_taskCnt, 1);
            if (slot < MAXTASK){ g_taskJ[slot] = ji; g_taskFlag[slot] = 0; }
        }
    }
    __syncthreads();
    if (tid == 0){ int c = g_taskCnt; if (c > MAXTASK) c = MAXTASK; g_taskCnt = c; sCnt = c; }
    __syncthreads();
    int cnt = sCnt;
    for (int t = tid; t < cnt; t += D)
        atomicCAS(&g_cellOwner[g_taskJ[t] / 42], 0, t + 1);
    __syncthreads();
    for (int t = tid; t < cnt; t += D){
        int bc = g_taskJ[t] / 42;
        if (g_cellOwner[bc] == t + 1){
            int s = atomicAdd(&g_siteCnt, 1);
            g_siteCell[s] = bc;
            g_siteOfTask[t] = s;
        }
    }
    __syncthreads();
    for (int t = tid; t < cnt; t += D)
        g_taskSite[t] = g_siteOfTask[g_cellOwner[g_taskJ[t] / 42] - 1];
}

// ---------------- KP: coalesced patch build ----------------
__global__ void kp(const float* __restrict__ fm){
    for (int s = blockIdx.x; s < g_siteCnt; s += 512){
        int bc = g_siteCell[s];
        int b = bc / MCELL, cell = bc % MCELL;
        int y = cell >> 6, x = cell & 63;
        for (int k = threadIdx.x; k < KPATCH; k += 256){
            int c = k / 9, r = k - c*9;
            int yy = y + r/3 - 1, xx = x + r%3 - 1;
            float v = 0.0f;
            if (yy >= 0 && yy < 64 && xx >= 0 && xx < 64)
                v = fm[((b*256 + c)*64 + yy)*64 + xx];
            g_patch[(size_t)s*KPATCH + k] = v;
        }
    }
}

// ---------------- K4: K-split GEMM, 64n x 64m tiles, packed f32x2 FMA ----------------
__global__ void k4(const float* __restrict__ W){
    int nS = g_siteCnt;
    int n0 = blockIdx.x * 64;
    if (n0 >= nS) return;
    int m0 = blockIdx.y * 64;
    int kb = blockIdx.z * KCH;
    __shared__ float As[16][64];
    __shared__ float Bs[16][64];
    int tid = threadIdx.x;
    int tx = tid & 15, ty = tid >> 4;
    int mm = tid >> 2, kq = (tid & 3) * 4;
    unsigned long long accp[2][4];   // m-pairs {01},{23} x 4 n; lanes = (m, m+1)
    #pragma unroll
    for (int i = 0; i < 2; i++)
        #pragma unroll
        for (int j = 0; j < 4; j++) accp[i][j] = pk2(0.0f, 0.0f);

    for (int kt = 0; kt < 36; kt++){
        int k0 = kb + kt*16;
        float4 a4 = *(const float4*)(W + (size_t)(m0+mm)*KPATCH + k0 + kq);
        float4 b4 = *(const float4*)(g_patch + (size_t)(n0+mm)*KPATCH + k0 + kq);
        As[kq+0][mm] = a4.x; As[kq+1][mm] = a4.y; As[kq+2][mm] = a4.z; As[kq+3][mm] = a4.w;
        Bs[kq+0][mm] = b4.x; Bs[kq+1][mm] = b4.y; Bs[kq+2][mm] = b4.z; Bs[kq+3][mm] = b4.w;
        __syncthreads();
        #pragma unroll
        for (int kk = 0; kk < 16; kk++){
            float4 av = *(const float4*)&As[kk][ty*4];
            float4 bv = *(const float4*)&Bs[kk][tx*4];
            unsigned long long p01 = pk2(av.x, av.y);
            unsigned long long p23 = pk2(av.z, av.w);
            unsigned long long bb0 = pk2(bv.x, bv.x);
            unsigned long long bb1 = pk2(bv.y, bv.y);
            unsigned long long bb2 = pk2(bv.z, bv.z);
            unsigned long long bb3 = pk2(bv.w, bv.w);
            fma2(accp[0][0], p01, bb0); fma2(accp[1][0], p23, bb0);
            fma2(accp[0][1], p01, bb1); fma2(accp[1][1], p23, bb1);
            fma2(accp[0][2], p01, bb2); fma2(accp[1][2], p23, bb2);
            fma2(accp[0][3], p01, bb3); fma2(accp[1][3], p23, bb3);
        }
        __syncthreads();
    }
    float* outz = g_hidP[blockIdx.z];
    #pragma unroll
    for (int j = 0; j < 4; j++){
        int n = n0 + tx*4 + j;
        if (n < nS){
            float v0, v1, v2, v3;
            upk2(v0, v1, accp[0][j]);
            upk2(v2, v3, accp[1][j]);
            float* o = outz + (size_t)n*512 + m0 + ty*4;
            o[0] = v0; o[1] = v1; o[2] = v2; o[3] = v3;
        }
    }
}

// ---------------- K5: heads (persistent grid); last block does final + reset ----------------
__global__ void k5(const float* __restrict__ conf_w, const float* __restrict__ conf_b,
                   const float* __restrict__ reg_w,  const float* __restrict__ reg_b,
                   const float* __restrict__ b1, float* out){
    __shared__ int sLast;
    int warp = threadIdx.x >> 5, lane = threadIdx.x & 31;
    int cnt = g_taskCnt; if (cnt > MAXTASK) cnt = MAXTASK;
    int nwarps = gridDim.x * 8;
    for (int t = blockIdx.x*8 + warp; t < cnt; t += nwarps){
        int j = g_taskJ[t];
        int a = j % 42;
        size_t hbase = (size_t)g_taskSite[t]*512;
        int isPos = g_taskFlag[t];
        float cacc = 0.0f, racc0 = 0.0f, racc1 = 0.0f, racc2 = 0.0f, racc3 = 0.0f;
        const float* cw = conf_w + a*512;
        const float* rw = reg_w + (a*4)*512;
        for (int c = lane; c < 512; c += 32){
            float hv = g_hidP[0][hbase+c] + g_hidP[1][hbase+c] + g_hidP[2][hbase+c] + g_hidP[3][hbase+c];
            hv = fmaxf(hv + b1[c], 0.0f);
            cacc += cw[c]*hv;
            if (isPos){
                racc0 += rw[c      ]*hv;
                racc1 += rw[c +  512]*hv;
                racc2 += rw[c + 1024]*hv;
                racc3 += rw[c + 1536]*hv;
            }
        }
        #pragma unroll
        for (int off = 16; off > 0; off >>= 1){
            cacc  += __shfl_down_sync(0xffffffffu, cacc,  off);
            racc0 += __shfl_down_sync(0xffffffffu, racc0, off);
            racc1 += __shfl_down_sync(0xffffffffu, racc1, off);
            racc2 += __shfl_down_sync(0xffffffffu, racc2, off);
            racc3 += __shfl_down_sync(0xffffffffu, racc3, off);
        }
        if (lane == 0){
            float conf = cacc + conf_b[a];
            if (isPos){
                atomicAdd(&g_accPos, softplusf(-conf));
                float rv[4] = {racc0 + reg_b[a*4+0], racc1 + reg_b[a*4+1],
                               racc2 + reg_b[a*4+2], racc3 + reg_b[a*4+3]};
                float s = 0.0f;
                #pragma unroll
                for (int d = 0; d < 4; d++){
                    float dd = rv[d] - g_taskOff[t*4+d];
                    float ad = fabsf(dd);
                    s += (ad < 1.0f) ? 0.5f*dd*dd : (ad - 0.5f);
                }
                atomicAdd(&g_accReg, s);
            } else {
                atomicAdd(&g_accNeg, softplusf(conf));
            }
        }
    }
    __syncthreads();
    if (threadIdx.x == 0){
        __threadfence();
        sLast = (atomicAdd(&g_doneH, 1) == gridDim.x - 1);
    }
    __syncthreads();
    if (!sLast) return;
    if (threadIdx.x == 0){
        float P = (float)g_P;
        out[0] = (P > 0.0f) ? 0.5f*(g_accPos/P + g_accNeg/P) + g_accReg/(P*4.0f) : 0.0f;
    }
    int tid = threadIdx.x;
    for (int t2 = tid; t2 < cnt; t2 += 256)
        g_cellOwner[g_taskJ[t2] / 42] = 0;
    for (int i = tid; i < 8*NGT; i += 256) g_maxgt[i] = 0u;
    if (tid == 0){
        g_candCnt = 0; g_taskCnt = 0; g_siteCnt = 0; g_P = 0;
        g_doneH = 0;
        g_accPos = 0.0f; g_accNeg = 0.0f; g_accReg = 0.0f;
    }
}

extern "C" void kernel_launch(void* const* d_in, const int* in_sizes, int n_in,
                              void* d_out, int out_size) {
    const float* fm      = (const float*)d_in[0];
    const float* gt      = (const float*)d_in[1];
    const float* conv1_w = (const float*)d_in[3];
    const float* conv1_b = (const float*)d_in[4];
    const float* conf_w  = (const float*)d_in[5];
    const float* conf_b  = (const float*)d_in[6];
    const float* reg_w   = (const float*)d_in[7];
    const float* reg_b   = (const float*)d_in[8];
    float* out = (float*)d_out;

    k1<<<TOTANC/512 + 8*REGY, 512>>>(gt);
    k2<<<8*REGY, 448>>>(gt);
    kp<<<512, 256>>>(fm);
    k4<<<dim3(128, 8, 4), 256>>>(conv1_w);
    k5<<<128, 256>>>(conf_w, conf_b, reg_w, reg_b, conv1_b, out);
}

// round 14
// speedup vs baseline: 1.1434x; 1.1434x over previous
#include <cuda_runtime.h>
#include <cuda_bf16.h>
#include <math.h>

#define NGT      20
#define MCELL    4096
#define MANC     (MCELL*42)
#define TOTANC   (8*MANC)
#define KPATCH   2304
#define MAXTASK  8192
#define MAXSITE  8192
#define PCAP     4096
#define CAND_MAX 32768
#define CAND_THR 131072u
#define TIE_MAX  256
#define REGY     10
#define REGX     10
#define NKCH     8
#define KCH      288         // KPATCH/8
#define NT_GRID  16

// ---- device state: ALL zero-init at load; K5 restores this state each replay ----
__device__ unsigned g_maxgt[8*NGT];
__device__ int      g_candCnt;
__device__ unsigned g_candU[CAND_MAX];
__device__ int      g_candJ[CAND_MAX];
__device__ int      g_taskCnt, g_siteCnt, g_P;
__device__ int      g_doneB, g_doneH;
__device__ int      g_taskJ[MAXTASK];
__device__ int      g_taskFlag[MAXTASK];
__device__ int      g_taskSite[MAXTASK];
__device__ float    g_taskOff[MAXTASK*4];
__device__ int      g_cellOwner[8*MCELL];      // 0 = unclaimed, else task+1
__device__ int      g_siteCell[MAXSITE];
__device__ int      g_siteOfTask[MAXTASK];
__device__ float    g_patch[(size_t)MAXSITE*KPATCH];
__device__ float    g_hidP[NKCH][(size_t)MAXSITE*512];
__device__ float    g_accPos, g_accNeg, g_accReg;

__device__ __forceinline__ unsigned rotl32(unsigned v, int d){ return (v<<d)|(v>>(32-d)); }

// JAX partitionable threefry: element j -> threefry2x32(key=(0,7),(0,j)); draw = (o0^o1)>>9
__device__ __forceinline__ unsigned threefry_u(unsigned j){
    unsigned x0 = 0u, x1 = j;
    const unsigned ks0 = 0u, ks1 = 7u, ks2 = 0x1BD11BDDu;
    x0 += ks0; x1 += ks1;
#define TF_R4(A,B,C,D) { x0+=x1; x1=rotl32(x1,A); x1^=x0; \
                         x0+=x1; x1=rotl32(x1,B); x1^=x0; \
                         x0+=x1; x1=rotl32(x1,C); x1^=x0; \
                         x0+=x1; x1=rotl32(x1,D); x1^=x0; }
    TF_R4(13,15,26,6);  x0 += ks1; x1 += ks2 + 1u;
    TF_R4(17,29,16,24); x0 += ks2; x1 += ks0 + 2u;
    TF_R4(13,15,26,6);  x0 += ks0; x1 += ks1 + 3u;
    TF_R4(17,29,16,24); x0 += ks1; x1 += ks2 + 4u;
    TF_R4(13,15,26,6);  x0 += ks2; x1 += ks0 + 5u;
#undef TF_R4
    return (x0 ^ x1) >> 9;
}

// IoU V1 — all plain RN, no contraction. Bit-exact vs reference. DO NOT CHANGE.
__device__ __forceinline__ float iou_one(float a0,float a1,float a2,float a3,
                                         float areaA,
                                         const float* g, float gw0, float gw1){
    float t0 = fmaxf(a0, g[0]), t1 = fmaxf(a1, g[1]);
    float q0 = fminf(a2, g[2]), q1 = fminf(a3, g[3]);
    float w0 = fmaxf(__fsub_rn(q0, t0), 0.0f);
    float w1 = fmaxf(__fsub_rn(q1, t1), 0.0f);
    float inter = __fmul_rn(w0, w1);
    float ag    = __fmul_rn(gw0, gw1);
    float sum   = __fadd_rn(areaA, ag);
    float den   = __fsub_rn(sum, inter);
    return __fdiv_rn(inter, den);
}

__device__ __forceinline__ float softplusf(float x){
    return fmaxf(x, 0.0f) + log1pf(expf(-fabsf(x)));
}

__device__ __forceinline__ void anc_coords(int a, int y, int x,
                                           float& a0, float& a1, float& a2, float& a3){
    const double SC[6] = {2.0, 2.5, 3.0, 3.5, 4.0, 5.0};
    const double RA[7] = {0.5, 1.5, 2.0, 2.5, 3.0, 3.5, 4.0};
    double s = SC[a/7], ar = RA[a%7];
    double h = (16.0*s) * sqrt(ar);
    double w = (16.0*s) * sqrt(1.0/ar);
    float b0 = (float)(8.0 - h/2.0);
    float b1 = (float)(8.0 - w/2.0);
    float b2 = (float)(8.0 + h/2.0);
    float b3 = (float)(8.0 + w/2.0);
    double sy = (double)(y*16), sx = (double)(x*16);
    a0 = (float)((double)b0 + sy);
    a1 = (float)((double)b1 + sx);
    a2 = (float)((double)b2 + sy);
    a3 = (float)((double)b3 + sx);
}

// ---------------- K1: threefry candidates || passA ----------------
__global__ void k1(const float* __restrict__ gt){
    if (blockIdx.x < TOTANC/512){
        int j = blockIdx.x*512 + threadIdx.x;
        unsigned u = threefry_u((unsigned)j);
        if (u < CAND_THR){
            int slot = atomicAdd(&g_candCnt, 1);
            if (slot < CAND_MAX){ g_candU[slot] = u; g_candJ[slot] = j; }
        }
        return;
    }
    __shared__ float sg[NGT][4];
    __shared__ int   sval[NGT];
    __shared__ float sgw[NGT][2];
    __shared__ unsigned smax[NGT];
    int tid = threadIdx.x;
    int pb = blockIdx.x - TOTANC/512;
    int b = pb / REGY, y = pb % REGY;
    if (tid < NGT*4){
        int n = tid >> 2, k = tid & 3;
        float r = gt[(b*NGT+n)*4 + k];
        sg[n][k] = (r == -1.0f) ? -1.0f : r * 0.0625f;
    }
    if (tid < NGT) smax[tid] = 0u;
    __syncthreads();
    if (tid < NGT){
        sval[tid] = (sg[tid][0] >= 0.0f) ? 1 : 0;
        sgw[tid][0] = __fsub_rn(sg[tid][2], sg[tid][0]);
        sgw[tid][1] = __fsub_rn(sg[tid][3], sg[tid][1]);
    }
    __syncthreads();
    int x = tid / 42, a = tid % 42;
    if (x < REGX){
        float a0,a1,a2,a3; anc_coords(a, y, x, a0,a1,a2,a3);
        float areaA = __fmul_rn(__fsub_rn(a2,a0), __fsub_rn(a3,a1));
        #pragma unroll
        for (int n = 0; n < NGT; n++){
            if (sval[n]){
                float v = iou_one(a0,a1,a2,a3, areaA, sg[n], sgw[n][0], sgw[n][1]);
                if (v > 0.0f) atomicMax(&smax[n], __float_as_uint(v));
            }
        }
    }
    __syncthreads();
    if (tid < NGT && smax[tid]) atomicMax(&g_maxgt[b*NGT + tid], smax[tid]);
}

// ---------------- K2: passB; last block freezes P AND runs select+tail inline ----------------
__global__ void k2(const float* __restrict__ gt){
    __shared__ float sg[NGT][4];
    __shared__ int   sval[NGT];
    __shared__ float sgw[NGT][2];
    __shared__ float smaxg[NGT];
    __shared__ int   sLast;
    __shared__ unsigned hist[1024];
    __shared__ unsigned h2[128];
    __shared__ int tieJ[TIE_MAX];
    __shared__ int sTie, sBin, sR2, sCnt;
    __shared__ unsigned sUstar, sC1;
    int tid = threadIdx.x;
    int D = blockDim.x;
    int b = blockIdx.x / REGY, y = blockIdx.x % REGY;
    if (tid < NGT*4){
        int n = tid >> 2, k = tid & 3;
        float r = gt[(b*NGT+n)*4 + k];
        sg[n][k] = (r == -1.0f) ? -1.0f : r * 0.0625f;
    }
    __syncthreads();
    if (tid < NGT){
        sval[tid] = (sg[tid][0] >= 0.0f) ? 1 : 0;
        sgw[tid][0] = __fsub_rn(sg[tid][2], sg[tid][0]);
        sgw[tid][1] = __fsub_rn(sg[tid][3], sg[tid][1]);
        smaxg[tid] = __uint_as_float(g_maxgt[b*NGT + tid]);
    }
    __syncthreads();
    int x = tid / 42, a = tid % 42;
    if (x < REGX){
        float a0,a1,a2,a3; anc_coords(a, y, x, a0,a1,a2,a3);
        float areaA = __fmul_rn(__fsub_rn(a2,a0), __fsub_rn(a3,a1));
        float best = -1.0f; int bestn = 0; bool pos = false;
        #pragma unroll
        for (int n = 0; n < NGT; n++){
            float v = sval[n] ? iou_one(a0,a1,a2,a3, areaA, sg[n], sgw[n][0], sgw[n][1]) : 0.0f;
            if (v > best){ best = v; bestn = n; }
            if (sval[n] && smaxg[n] > 0.0f && v == smaxg[n]) pos = true;
        }
        if (pos){
            int slot = atomicAdd(&g_taskCnt, 1);
            if (slot < MAXTASK){
                int j = ((b*MCELL) + y*64 + x)*42 + a;
                g_taskJ[slot] = j;
                g_taskFlag[slot] = 1;
                const float* G = sg[bestn];
                float acy = __fmul_rn(__fadd_rn(a0, a2), 0.5f);
                float acx = __fmul_rn(__fadd_rn(a1, a3), 0.5f);
                float asy = __fsub_rn(a2, a0), asx = __fsub_rn(a3, a1);
                float gcy = __fmul_rn(__fadd_rn(G[0], G[2]), 0.5f);
                float gcx = __fmul_rn(__fadd_rn(G[1], G[3]), 0.5f);
                float gsy = __fsub_rn(G[2], G[0]), gsx = __fsub_rn(G[3], G[1]);
                g_taskOff[slot*4+0] = __fdiv_rn(__fsub_rn(gcy, acy), asy);
                g_taskOff[slot*4+1] = __fdiv_rn(__fsub_rn(gcx, acx), asx);
                g_taskOff[slot*4+2] = logf(__fdiv_rn(gsy, asy));
                g_taskOff[slot*4+3] = logf(__fdiv_rn(gsx, asx));
            }
        }
    }
    __syncthreads();
    if (tid == 0){
        __threadfence();
        sLast = (atomicAdd(&g_doneB, 1) == gridDim.x - 1);
    }
    __syncthreads();
    if (!sLast) return;

    // ======== last block: freeze P, then select + tail ========
    if (tid == 0){
        int P = g_taskCnt; if (P > PCAP) P = PCAP;
        g_P = P; g_doneB = 0; sTie = 0;
    }
    for (int i = tid; i < 1024; i += D) hist[i] = 0u;
    __syncthreads();
    int C = g_candCnt; if (C > CAND_MAX) C = CAND_MAX;
    int P = g_P;
    if (P > 0){
        for (int i = tid; i < C; i += D) atomicAdd(&hist[g_candU[i] >> 7], 1u);
    }
    __syncthreads();
    if (tid == 0){
        int bin = -1; unsigned cum = 0;
        if (P > 0){
            for (int q = 0; q < 1024; q++){
                unsigned h = hist[q];
                if (cum + h >= (unsigned)P){ bin = q; break; }
                cum += h;
            }
        }
        sBin = bin; sC1 = cum;
    }
    __syncthreads();
    int bin = sBin;
    unsigned C1 = sC1;
    for (int i = tid; i < 128; i += D) h2[i] = 0u;
    __syncthreads();
    if (bin >= 0){
        for (int i = tid; i < C; i += D){
            unsigned u = g_candU[i];
            if ((int)(u >> 7) == bin) atomicAdd(&h2[u & 127u], 1u);
        }
    }
    __syncthreads();
    if (tid == 0 && bin >= 0){
        unsigned cum = C1; int vS = 0; unsigned Cless = C1;
        for (int v = 0; v < 128; v++){
            unsigned c = h2[v];
            if (cum + c >= (unsigned)P){ vS = v; Cless = cum; break; }
            cum += c;
        }
        sUstar = ((unsigned)bin << 7) | (unsigned)vS;
        sR2 = P - (int)Cless;
    }
    __syncthreads();
    if (bin >= 0){
        unsigned us = sUstar;
        for (int i = tid; i < C; i += D){
            unsigned u = g_candU[i];
            if (u < us){
                int slot = atomicAdd(&g_taskCnt, 1);
                if (slot < MAXTASK){ g_taskJ[slot] = g_candJ[i]; g_taskFlag[slot] = 0; }
            } else if (u == us){
                int t = atomicAdd(&sTie, 1);
                if (t < TIE_MAX) tieJ[t] = g_candJ[i];
            }
        }
    }
    __syncthreads();
    int T = sTie; if (T > TIE_MAX) T = TIE_MAX;
    int R2 = (bin >= 0) ? sR2 : 0;
    for (int i = tid; i < T; i += D){
        int ji = tieJ[i], rank = 0;
        for (int q = 0; q < T; q++) if (tieJ[q] < ji) rank++;
        if (rank < R2){
            int slot = atomicAdd(&g_taskCnt, 1);
            if (slot < MAXTASK){ g_taskJ[slot] = ji; g_taskFlag[slot] = 0; }
        }
    }
    __syncthreads();
    if (tid == 0){ int c = g_taskCnt; if (c > MAXTASK) c = MAXTASK; g_taskCnt = c; sCnt = c; }
    __syncthreads();
    int cnt = sCnt;
    for (int t = tid; t < cnt; t += D)
        atomicCAS(&g_cellOwner[g_taskJ[t] / 42], 0, t + 1);
    __syncthreads();
    for (int t = tid; t < cnt; t += D){
        int bc = g_taskJ[t] / 42;
        if (g_cellOwner[bc] == t + 1){
            int s = atomicAdd(&g_siteCnt, 1);
            g_siteCell[s] = bc;
            g_siteOfTask[t] = s;
        }
    }
    __syncthreads();
    for (int t = tid; t < cnt; t += D)
        g_taskSite[t] = g_siteOfTask[g_cellOwner[g_taskJ[t] / 42] - 1];
}

// ---------------- KP: coalesced patch build ----------------
__global__ void kp(const float* __restrict__ fm){
    for (int s = blockIdx.x; s < g_siteCnt; s += 512){
        int bc = g_siteCell[s];
        int b = bc / MCELL, cell = bc % MCELL;
        int y = cell >> 6, x = cell & 63;
        for (int k = threadIdx.x; k < KPATCH; k += 256){
            int c = k / 9, r = k - c*9;
            int yy = y + r/3 - 1, xx = x + r%3 - 1;
            float v = 0.0f;
            if (yy >= 0 && yy < 64 && xx >= 0 && xx < 64)
                v = fm[((b*256 + c)*64 + yy)*64 + xx];
            g_patch[(size_t)s*KPATCH + k] = v;
        }
    }
}

// ---------------- K4: K-split GEMM, 64n x 64m tiles, 4x4 acc, persistent n-loop ----------------
// grid (NT_GRID, 8 m-tiles, 8 k-chunks), 256 threads
__global__ void k4(const float* __restrict__ W){
    int nS = g_siteCnt;
    int m0 = blockIdx.y * 64;
    int kb = blockIdx.z * KCH;
    __shared__ float As[16][64];
    __shared__ float Bs[16][64];
    int tid = threadIdx.x;
    int tx = tid & 15, ty = tid >> 4;
    int mm = tid >> 2, kq = (tid & 3) * 4;
    float* outz = g_hidP[blockIdx.z];

    for (int nt = blockIdx.x; nt*64 < nS; nt += NT_GRID){
        int n0 = nt*64;
        float acc[4][4];
        #pragma unroll
        for (int i = 0; i < 4; i++)
            #pragma unroll
            for (int j = 0; j < 4; j++) acc[i][j] = 0.0f;

        for (int kt = 0; kt < KCH/16; kt++){
            int k0 = kb + kt*16;
            float4 a4 = *(const float4*)(W + (size_t)(m0+mm)*KPATCH + k0 + kq);
            float4 b4 = *(const float4*)(g_patch + (size_t)(n0+mm)*KPATCH + k0 + kq);
            As[kq+0][mm] = a4.x; As[kq+1][mm] = a4.y; As[kq+2][mm] = a4.z; As[kq+3][mm] = a4.w;
            Bs[kq+0][mm] = b4.x; Bs[kq+1][mm] = b4.y; Bs[kq+2][mm] = b4.z; Bs[kq+3][mm] = b4.w;
            __syncthreads();
            #pragma unroll
            for (int kk = 0; kk < 16; kk++){
                float4 av = *(const float4*)&As[kk][ty*4];
                float4 bv = *(const float4*)&Bs[kk][tx*4];
                float a[4] = {av.x, av.y, av.z, av.w};
                float b[4] = {bv.x, bv.y, bv.z, bv.w};
                #pragma unroll
                for (int i = 0; i < 4; i++)
                    #pragma unroll
                    for (int j = 0; j < 4; j++) acc[i][j] += a[i]*b[j];
            }
            __syncthreads();
        }
        #pragma unroll
        for (int j = 0; j < 4; j++){
            int n = n0 + tx*4 + j;
            if (n < nS){
                #pragma unroll
                for (int i = 0; i < 4; i++)
                    outz[(size_t)n*512 + m0 + ty*4 + i] = acc[i][j];
            }
        }
    }
}

// ---------------- K5: heads (persistent grid); last block does final + reset ----------------
__global__ void k5(const float* __restrict__ conf_w, const float* __restrict__ conf_b,
                   const float* __restrict__ reg_w,  const float* __restrict__ reg_b,
                   const float* __restrict__ b1, float* out){
    __shared__ int sLast;
    int warp = threadIdx.x >> 5, lane = threadIdx.x & 31;
    int cnt = g_taskCnt; if (cnt > MAXTASK) cnt = MAXTASK;
    int nwarps = gridDim.x * 8;
    for (int t = blockIdx.x*8 + warp; t < cnt; t += nwarps){
        int j = g_taskJ[t];
        int a = j % 42;
        size_t hbase = (size_t)g_taskSite[t]*512;
        int isPos = g_taskFlag[t];
        float cacc = 0.0f, racc0 = 0.0f, racc1 = 0.0f, racc2 = 0.0f, racc3 = 0.0f;
        const float* cw = conf_w + a*512;
        const float* rw = reg_w + (a*4)*512;
        for (int c = lane; c < 512; c += 32){
            float hv = 0.0f;
            #pragma unroll
            for (int z = 0; z < NKCH; z++) hv += g_hidP[z][hbase+c];
            hv = fmaxf(hv + b1[c], 0.0f);
            cacc += cw[c]*hv;
            if (isPos){
                racc0 += rw[c      ]*hv;
                racc1 += rw[c +  512]*hv;
                racc2 += rw[c + 1024]*hv;
                racc3 += rw[c + 1536]*hv;
            }
        }
        #pragma unroll
        for (int off = 16; off > 0; off >>= 1){
            cacc  += __shfl_down_sync(0xffffffffu, cacc,  off);
            racc0 += __shfl_down_sync(0xffffffffu, racc0, off);
            racc1 += __shfl_down_sync(0xffffffffu, racc1, off);
            racc2 += __shfl_down_sync(0xffffffffu, racc2, off);
            racc3 += __shfl_down_sync(0xffffffffu, racc3, off);
        }
        if (lane == 0){
            float conf = cacc + conf_b[a];
            if (isPos){
                atomicAdd(&g_accPos, softplusf(-conf));
                float rv[4] = {racc0 + reg_b[a*4+0], racc1 + reg_b[a*4+1],
                               racc2 + reg_b[a*4+2], racc3 + reg_b[a*4+3]};
                float s = 0.0f;
                #pragma unroll
                for (int d = 0; d < 4; d++){
                    float dd = rv[d] - g_taskOff[t*4+d];
                    float ad = fabsf(dd);
                    s += (ad < 1.0f) ? 0.5f*dd*dd : (ad - 0.5f);
                }
                atomicAdd(&g_accReg, s);
            } else {
                atomicAdd(&g_accNeg, softplusf(conf));
            }
        }
    }
    __syncthreads();
    if (threadIdx.x == 0){
        __threadfence();
        sLast = (atomicAdd(&g_doneH, 1) == gridDim.x - 1);
    }
    __syncthreads();
    if (!sLast) return;
    if (threadIdx.x == 0){
        float P = (float)g_P;
        out[0] = (P > 0.0f) ? 0.5f*(g_accPos/P + g_accNeg/P) + g_accReg/(P*4.0f) : 0.0f;
    }
    int tid = threadIdx.x;
    for (int t2 = tid; t2 < cnt; t2 += 256)
        g_cellOwner[g_taskJ[t2] / 42] = 0;
    for (int i = tid; i < 8*NGT; i += 256) g_maxgt[i] = 0u;
    if (tid == 0){
        g_candCnt = 0; g_taskCnt = 0; g_siteCnt = 0; g_P = 0;
        g_doneH = 0;
        g_accPos = 0.0f; g_accNeg = 0.0f; g_accReg = 0.0f;
    }
}

extern "C" void kernel_launch(void* const* d_in, const int* in_sizes, int n_in,
                              void* d_out, int out_size) {
    const float* fm      = (const float*)d_in[0];
    const float* gt      = (const float*)d_in[1];
    const float* conv1_w = (const float*)d_in[3];
    const float* conv1_b = (const float*)d_in[4];
    const float* conf_w  = (const float*)d_in[5];
    const float* conf_b  = (const float*)d_in[6];
    const float* reg_w   = (const float*)d_in[7];
    const float* reg_b   = (const float*)d_in[8];
    float* out = (float*)d_out;

    k1<<<TOTANC/512 + 8*REGY, 512>>>(gt);
    k2<<<8*REGY, 448>>>(gt);
    kp<<<512, 256>>>(fm);
    k4<<<dim3(NT_GRID, 8, NKCH), 256>>>(conv1_w);
    k5<<<128, 256>>>(conf_w, conf_b, reg_w, reg_b, conv1_b, out);
}